// round 2
// baseline (speedup 1.0000x reference)
#include <cuda_runtime.h>
#include <math.h>

#define G 32
#define NPTS (G*G*G)
#define MAXF 2048
#define NSLICE 37
#define FCHUNK 64
#define EPSF 1e-12f
#define BIGF 1e30f

// ---------------- device scratch (no allocations allowed) ----------------
__device__ float g_params[8];              // cx, cy, cz, scale, overlap
__device__ float g_face[21 * MAXF];        // SoA per-face precompute
__device__ float g_pd2[NSLICE * NPTS];     // partial min squared distance
__device__ int   g_phit[NSLICE * NPTS];    // partial ray-cast hit counts
__device__ float g_phi[NPTS];              // phi grid [z,y,x]

// field indices in g_face
enum {
    F_V0X=0, F_V0Y, F_V0Z, F_E0X, F_E0Y, F_E0Z, F_E1X, F_E1Y, F_E1Z,
    F_A, F_B, F_C, F_INVA, F_INVC, F_INVDET, F_DETOK,
    F_EE2, F_INVEE2, F_BMA, F_DET2S, F_OK2, F_NFIELD
};

__device__ __forceinline__ float grid_coord(int i) {
    // jnp.linspace(-1, 1, 32): start + iota*delta, endpoint set exactly
    const float step = 2.0f / 31.0f;
    if (i == G - 1) return 1.0f;
    return __fadd_rn(-1.0f, __fmul_rn((float)i, step));
}

// ---------------- K1: bboxes -> center/scale/overlap ----------------
__device__ __forceinline__ float blockRed256(float v, bool isMin) {
    __shared__ float sm[256];
    __syncthreads();
    sm[threadIdx.x] = v;
    __syncthreads();
    for (int s = 128; s > 0; s >>= 1) {
        if (threadIdx.x < s) {
            float o = sm[threadIdx.x + s];
            sm[threadIdx.x] = isMin ? fminf(sm[threadIdx.x], o)
                                    : fmaxf(sm[threadIdx.x], o);
        }
        __syncthreads();
    }
    return sm[0];
}

__global__ void k_bbox(const float* __restrict__ hv, int nh,
                       const float* __restrict__ ov, int no) {
    int t = threadIdx.x;
    float hmn[3] = { BIGF,  BIGF,  BIGF};
    float hmx[3] = {-BIGF, -BIGF, -BIGF};
    float omn[3] = { BIGF,  BIGF,  BIGF};
    float omx[3] = {-BIGF, -BIGF, -BIGF};
    for (int i = t; i < nh; i += 256) {
        #pragma unroll
        for (int c = 0; c < 3; c++) {
            float x = hv[i*3 + c];
            hmn[c] = fminf(hmn[c], x);
            hmx[c] = fmaxf(hmx[c], x);
        }
    }
    for (int i = t; i < no; i += 256) {
        #pragma unroll
        for (int c = 0; c < 3; c++) {
            float x = ov[i*3 + c];
            omn[c] = fminf(omn[c], x);
            omx[c] = fmaxf(omx[c], x);
        }
    }
    float bminh[3], bmaxh[3], bmino[3], bmaxo[3];
    #pragma unroll
    for (int c = 0; c < 3; c++) {
        bminh[c] = blockRed256(hmn[c], true);
        bmaxh[c] = blockRed256(hmx[c], false);
        bmino[c] = blockRed256(omn[c], true);
        bmaxo[c] = blockRed256(omx[c], false);
    }
    if (t == 0) {
        float cx = __fmul_rn(0.5f, __fadd_rn(bminh[0], bmaxh[0]));
        float cy = __fmul_rn(0.5f, __fadd_rn(bminh[1], bmaxh[1]));
        float cz = __fmul_rn(0.5f, __fadd_rn(bminh[2], bmaxh[2]));
        float ext = fmaxf(fmaxf(__fsub_rn(bmaxh[0], bminh[0]),
                                __fsub_rn(bmaxh[1], bminh[1])),
                          __fsub_rn(bmaxh[2], bminh[2]));
        // (1 + 0.2) * 0.5 in fp32 == 0.6f exactly
        float scale = __fmul_rn(0.6f, ext);
        bool ovl = true;
        #pragma unroll
        for (int c = 0; c < 3; c++) {
            ovl = ovl && (bminh[c] <= bmaxo[c]) && (bmino[c] <= bmaxh[c]);
        }
        g_params[0] = cx; g_params[1] = cy; g_params[2] = cz;
        g_params[3] = scale;
        g_params[4] = ovl ? 1.0f : 0.0f;
    }
}

// ---------------- K2: per-face precompute ----------------
__global__ void k_faces(const float* __restrict__ hv,
                        const int* __restrict__ faces, int F) {
    int f = blockIdx.x * blockDim.x + threadIdx.x;
    if (f >= F) return;
    float cx = g_params[0], cy = g_params[1], cz = g_params[2];
    float sc = g_params[3];
    int i0 = faces[f*3+0], i1 = faces[f*3+1], i2 = faces[f*3+2];
    float v0x = __fdiv_rn(__fsub_rn(hv[i0*3+0], cx), sc);
    float v0y = __fdiv_rn(__fsub_rn(hv[i0*3+1], cy), sc);
    float v0z = __fdiv_rn(__fsub_rn(hv[i0*3+2], cz), sc);
    float v1x = __fdiv_rn(__fsub_rn(hv[i1*3+0], cx), sc);
    float v1y = __fdiv_rn(__fsub_rn(hv[i1*3+1], cy), sc);
    float v1z = __fdiv_rn(__fsub_rn(hv[i1*3+2], cz), sc);
    float v2x = __fdiv_rn(__fsub_rn(hv[i2*3+0], cx), sc);
    float v2y = __fdiv_rn(__fsub_rn(hv[i2*3+1], cy), sc);
    float v2z = __fdiv_rn(__fsub_rn(hv[i2*3+2], cz), sc);
    float e0x = __fsub_rn(v1x, v0x), e0y = __fsub_rn(v1y, v0y), e0z = __fsub_rn(v1z, v0z);
    float e1x = __fsub_rn(v2x, v0x), e1y = __fsub_rn(v2y, v0y), e1z = __fsub_rn(v2z, v0z);
    float a = e0x*e0x + e0y*e0y + e0z*e0z;
    float b = e0x*e1x + e0y*e1y + e0z*e1z;
    float c = e1x*e1x + e1y*e1y + e1z*e1z;
    float det = a*c - b*b;
    float invdet = 1.0f / ((det > EPSF) ? det : 1.0f);
    float detok  = (det > EPSF) ? 1.0f : 0.0f;
    float inva = 1.0f / ((a > EPSF) ? a : 1.0f);
    float invc = 1.0f / ((c > EPSF) ? c : 1.0f);
    float ee2 = a + c - 2.0f*b;
    float invee2 = 1.0f / ((ee2 > EPSF) ? ee2 : 1.0f);
    float bma = b - a;
    // 2D projected determinant — exact-match path (no FMA contraction)
    float det2 = __fsub_rn(__fmul_rn(e0x, e1y), __fmul_rn(e1x, e0y));
    float ok2 = (fabsf(det2) > EPSF) ? 1.0f : 0.0f;
    float det2s = (fabsf(det2) > EPSF) ? det2 : 1.0f;

    g_face[F_V0X*MAXF+f] = v0x;  g_face[F_V0Y*MAXF+f] = v0y;  g_face[F_V0Z*MAXF+f] = v0z;
    g_face[F_E0X*MAXF+f] = e0x;  g_face[F_E0Y*MAXF+f] = e0y;  g_face[F_E0Z*MAXF+f] = e0z;
    g_face[F_E1X*MAXF+f] = e1x;  g_face[F_E1Y*MAXF+f] = e1y;  g_face[F_E1Z*MAXF+f] = e1z;
    g_face[F_A*MAXF+f] = a;      g_face[F_B*MAXF+f] = b;      g_face[F_C*MAXF+f] = c;
    g_face[F_INVA*MAXF+f] = inva;     g_face[F_INVC*MAXF+f] = invc;
    g_face[F_INVDET*MAXF+f] = invdet; g_face[F_DETOK*MAXF+f] = detok;
    g_face[F_EE2*MAXF+f] = ee2;       g_face[F_INVEE2*MAXF+f] = invee2;
    g_face[F_BMA*MAXF+f] = bma;
    g_face[F_DET2S*MAXF+f] = det2s;   g_face[F_OK2*MAXF+f] = ok2;
}

// ---------------- K3: phi grid (dominant kernel) ----------------
// 4 z-points per thread, NSLICE face slices, FCHUNK-face SMEM tiles.
// grid: 32*NSLICE blocks of 256 threads (= 1184 = 8 full waves of 148 SMs).
__global__ __launch_bounds__(256) void k_phi(int F) {
    const int FS = (F + NSLICE - 1) / NSLICE;
    int s = blockIdx.x / 32;                        // face slice
    int p = ((blockIdx.x & 31) << 8) | threadIdx.x; // point group id [0,8192)
    int x  = p & 31;
    int y  = (p >> 5) & 31;
    int zb = p >> 10;                               // 0..7

    float px = grid_coord(x);
    float py = grid_coord(y);
    float pz[4];
    #pragma unroll
    for (int k = 0; k < 4; k++) pz[k] = grid_coord(zb + 8*k);

    float d2min[4] = {BIGF, BIGF, BIGF, BIGF};
    int hits[4] = {0, 0, 0, 0};

    __shared__ float sf[F_NFIELD][FCHUNK];

    int fbeg = s * FS;
    int fend = min(F, fbeg + FS);
    for (int f0 = fbeg; f0 < fend; f0 += FCHUNK) {
        int nf = min(FCHUNK, fend - f0);
        __syncthreads();
        for (int i = threadIdx.x; i < F_NFIELD * FCHUNK; i += 256) {
            int fld = i / FCHUNK;
            int j   = i % FCHUNK;
            if (j < nf) sf[fld][j] = g_face[fld * MAXF + f0 + j];
        }
        __syncthreads();

        for (int j = 0; j < nf; j++) {
            float v0x = sf[F_V0X][j], v0y = sf[F_V0Y][j], v0z = sf[F_V0Z][j];
            float e0x = sf[F_E0X][j], e0y = sf[F_E0Y][j], e0z = sf[F_E0Z][j];
            float e1x = sf[F_E1X][j], e1y = sf[F_E1Y][j], e1z = sf[F_E1Z][j];
            float a = sf[F_A][j], b = sf[F_B][j], c = sf[F_C][j];
            float inva = sf[F_INVA][j], invc = sf[F_INVC][j];
            float invdet = sf[F_INVDET][j], detok = sf[F_DETOK][j];
            float ee2 = sf[F_EE2][j], invee2 = sf[F_INVEE2][j], bma = sf[F_BMA][j];
            float det2s = sf[F_DET2S][j], ok2 = sf[F_OK2][j];

            float wx = __fsub_rn(px, v0x);
            float wy = __fsub_rn(py, v0y);

            // --- ray cast: bit-matched to reference (IEEE div, no contraction) ---
            float nu = __fsub_rn(__fmul_rn(wx, e1y), __fmul_rn(wy, e1x));
            float nv = __fsub_rn(__fmul_rn(e0x, wy), __fmul_rn(e0y, wx));
            float u2 = __fdiv_rn(nu, det2s);
            float v2 = __fdiv_rn(nv, det2s);
            bool in2d = (u2 >= 0.0f) && (v2 >= 0.0f)
                     && (__fadd_rn(u2, v2) <= 1.0f) && (ok2 > 0.5f);
            float zint = __fadd_rn(__fadd_rn(v0z, __fmul_rn(u2, e0z)),
                                   __fmul_rn(v2, e1z));

            // --- distance: fast path (continuous, contraction OK) ---
            float s0  = wx*e0x + wy*e0y;     // de0 base
            float s1  = wx*e1x + wy*e1y;     // de1 base
            float fxy = wx*wx + wy*wy;       // f base

            #pragma unroll
            for (int k = 0; k < 4; k++) {
                float wz  = pz[k] - v0z;
                float de0 = s0 + wz*e0z;
                float de1 = s1 + wz*e1z;
                float ff  = fxy + wz*wz;
                float u = (c*de0 - b*de1) * invdet;
                float v = (a*de1 - b*de0) * invdet;
                bool ins = (u >= 0.0f) && (v >= 0.0f) && (u + v <= 1.0f) && (detok > 0.5f);
                float plane = ff - (u*de0 + v*de1);
                float de0_2 = de0 + de0;
                float de1_2 = de1 + de1;
                float t0 = fminf(fmaxf(de0*inva, 0.0f), 1.0f);
                float d0 = ff + t0*(t0*a - de0_2);
                float t1 = fminf(fmaxf(de1*invc, 0.0f), 1.0f);
                float d1 = ff + t1*(t1*c - de1_2);
                float dot2 = de1 - de0 - bma;
                float w1sq = ff - de0_2 + a;
                float t2 = fminf(fmaxf(dot2*invee2, 0.0f), 1.0f);
                float d22 = w1sq + t2*(t2*ee2 - (dot2 + dot2));
                float ed = fminf(fminf(d0, d1), d22);
                float d2 = ins ? plane : ed;
                d2 = fmaxf(d2, 0.0f);
                d2min[k] = fminf(d2min[k], d2);
                hits[k] += (in2d && (zint > pz[k])) ? 1 : 0;
            }
        }
    }

    #pragma unroll
    for (int k = 0; k < 4; k++) {
        int z = zb + 8*k;
        int n = ((z << 5) | y) * 32 + x;   // [z,y,x] layout
        g_pd2[s * NPTS + n]  = d2min[k];
        g_phit[s * NPTS + n] = hits[k];
    }
}

// ---------------- K4: combine slices -> phi ----------------
__global__ void k_combine() {
    int n = blockIdx.x * 256 + threadIdx.x;
    float d2 = BIGF;
    int h = 0;
    for (int s = 0; s < NSLICE; s++) {
        d2 = fminf(d2, g_pd2[s * NPTS + n]);
        h += g_phit[s * NPTS + n];
    }
    g_phi[n] = __fsqrt_rn(d2) * ((h & 1) ? 1.0f : 0.0f);
}

// ---------------- K5: trilinear sample + reduce + loss ----------------
__global__ void k_loss(const float* __restrict__ ov, int no,
                       float* __restrict__ out) {
    __shared__ float red[512];
    int t = threadIdx.x;
    float cx = g_params[0], cy = g_params[1], cz = g_params[2];
    float sc = g_params[3], ovl = g_params[4];
    float acc = 0.0f;
    for (int i = t; i < no; i += 512) {
        float qx = __fdiv_rn(__fsub_rn(ov[i*3+0], cx), sc);
        float qy = __fdiv_rn(__fsub_rn(ov[i*3+1], cy), sc);
        float qz = __fdiv_rn(__fsub_rn(ov[i*3+2], cz), sc);
        float fx = __fmul_rn(__fmul_rn(__fadd_rn(qx, 1.0f), 0.5f), (float)(G - 1));
        float fy = __fmul_rn(__fmul_rn(__fadd_rn(qy, 1.0f), 0.5f), (float)(G - 1));
        float fz = __fmul_rn(__fmul_rn(__fadd_rn(qz, 1.0f), 0.5f), (float)(G - 1));
        float flx = floorf(fx), fly = floorf(fy), flz = floorf(fz);
        int ix0 = (int)flx, iy0 = (int)fly, iz0 = (int)flz;
        float wx1 = __fsub_rn(fx, flx), wy1 = __fsub_rn(fy, fly), wz1 = __fsub_rn(fz, flz);
        float wx0 = __fsub_rn(1.0f, wx1), wy0 = __fsub_rn(1.0f, wy1), wz0 = __fsub_rn(1.0f, wz1);
        float val = 0.0f;
        #pragma unroll
        for (int dz = 0; dz < 2; dz++) {
            #pragma unroll
            for (int dy = 0; dy < 2; dy++) {
                #pragma unroll
                for (int dx = 0; dx < 2; dx++) {
                    int ix = ix0 + dx, iy = iy0 + dy, iz = iz0 + dz;
                    bool valid = (ix >= 0) && (ix < G) && (iy >= 0) && (iy < G)
                              && (iz >= 0) && (iz < G);
                    int cix = min(max(ix, 0), G-1);
                    int ciy = min(max(iy, 0), G-1);
                    int ciz = min(max(iz, 0), G-1);
                    float pv = g_phi[(ciz * G + ciy) * G + cix];
                    float w = __fmul_rn(__fmul_rn(dx ? wx1 : wx0, dy ? wy1 : wy0),
                                        dz ? wz1 : wz0);
                    val = __fadd_rn(val, valid ? __fmul_rn(pv, w) : 0.0f);
                }
            }
        }
        acc += val;
    }
    red[t] = acc;
    __syncthreads();
    for (int s = 256; s > 0; s >>= 1) {
        if (t < s) red[t] += red[t + s];
        __syncthreads();
    }
    if (t == 0) {
        float sum = red[0];
        float loss = __fmul_rn(sum, sum);
        out[0] = (ovl > 0.5f) ? loss : 0.0f;
    }
}

// ---------------- launch ----------------
extern "C" void kernel_launch(void* const* d_in, const int* in_sizes, int n_in,
                              void* d_out, int out_size) {
    const float* hv    = (const float*)d_in[0];
    const float* ov    = (const float*)d_in[1];
    const int*   faces = (const int*)d_in[2];
    int nh = in_sizes[0] / 3;
    int no = in_sizes[1] / 3;
    int F  = in_sizes[2] / 3;
    if (F > MAXF) F = MAXF;

    k_bbox<<<1, 256>>>(hv, nh, ov, no);
    k_faces<<<(F + 127) / 128, 128>>>(hv, faces, F);
    k_phi<<<32 * NSLICE, 256>>>(F);
    k_combine<<<NPTS / 256, 256>>>();
    k_loss<<<1, 512>>>(ov, no, (float*)d_out);
}

// round 4
// speedup vs baseline: 1.2063x; 1.2063x over previous
#include <cuda_runtime.h>
#include <math.h>

#define G 32
#define NPTS (G*G*G)
#define MAXF 2048
#define NSLICE 37
#define FCHUNK 64
#define EPSF 1e-12f
#define BIGF 1e30f

typedef unsigned long long ull;

// ---------------- packed f32x2 helpers (sm_103a: only fma/mul/add exist) ----
__device__ __forceinline__ ull fma2(ull a, ull b, ull c) {
    ull d; asm("fma.rn.f32x2 %0, %1, %2, %3;" : "=l"(d) : "l"(a), "l"(b), "l"(c)); return d;
}
__device__ __forceinline__ ull mul2(ull a, ull b) {
    ull d; asm("mul.rn.f32x2 %0, %1, %2;" : "=l"(d) : "l"(a), "l"(b)); return d;
}
__device__ __forceinline__ ull add2(ull a, ull b) {
    ull d; asm("add.rn.f32x2 %0, %1, %2;" : "=l"(d) : "l"(a), "l"(b)); return d;
}
__device__ __forceinline__ ull pack2(float lo, float hi) {
    ull d; asm("mov.b64 %0, {%1, %2};" : "=l"(d) : "f"(lo), "f"(hi)); return d;
}
__device__ __forceinline__ void unpack2(float& lo, float& hi, ull v) {
    asm("mov.b64 {%0, %1}, %2;" : "=f"(lo), "=f"(hi) : "l"(v));
}
// emulated packed min/max: 2x FMNMX on the register-pair halves
__device__ __forceinline__ ull min2(ull a, ull b) {
    float al, ah, bl, bh;
    unpack2(al, ah, a); unpack2(bl, bh, b);
    return pack2(fminf(al, bl), fminf(ah, bh));
}
__device__ __forceinline__ ull max2(ull a, ull b) {
    float al, ah, bl, bh;
    unpack2(al, ah, a); unpack2(bl, bh, b);
    return pack2(fmaxf(al, bl), fmaxf(ah, bh));
}

#define ONE2    0x3F8000003F800000ULL
#define M1_2    0xBF800000BF800000ULL
#define MTWO2   0xC0000000C0000000ULL
#define ZERO2   0ULL
#define NEGBIG2 0xF149F2CAF149F2CAULL   // (-1e30f, -1e30f)

// ---------------- device scratch ----------------
__device__ float g_params[8];               // cx, cy, cz, scale, overlap
__device__ float g_face[22 * MAXF];         // SoA per-face precompute
__device__ uint2 g_slice[NSLICE * NPTS];    // (d2 bits, hits) per slice per point
__device__ float g_phi[NPTS];               // phi grid [z,y,x]
__device__ float g_lpart[8];                // loss partial sums

// scalar field indices in g_face (F_DET holds det' = detok ? det : -BIG)
enum {
    F_V0X=0, F_V0Y, F_V0Z, F_E0X, F_E0Y, F_E0Z, F_E1X, F_E1Y, F_E1Z,
    F_A, F_B, F_C, F_INVA, F_INVC, F_INVDET, F_DET,
    F_EE2, F_INVEE2, F_BMA, F_DET2S, F_OK2, F_NFIELD
};

// packed smem fields
enum {
    PK_NV0Z=0, PK_E0Z, PK_E1Z, PK_A, PK_NB, PK_C, PK_INVA, PK_INVC,
    PK_NINVDET, PK_EE2, PK_INVEE2, PK_DZ10, PK_DETP, PK_N
};
// scalar smem fields
enum {
    SC_V0X=0, SC_V0Y, SC_V0Z, SC_E0X, SC_E0Y, SC_E0Z, SC_E1X, SC_E1Y,
    SC_E1Z, SC_DET2S, SC_OK2, SC_BMA, SC_N
};

__device__ __forceinline__ float grid_coord(int i) {
    const float step = 2.0f / 31.0f;
    if (i == G - 1) return 1.0f;
    return __fadd_rn(-1.0f, __fmul_rn((float)i, step));
}

// ---------------- K1: fused bbox + face precompute (one CTA) ----------------
__device__ __forceinline__ float blockRed256(float v, bool isMin) {
    __shared__ float sm[256];
    __syncthreads();
    sm[threadIdx.x] = v;
    __syncthreads();
    for (int s = 128; s > 0; s >>= 1) {
        if (threadIdx.x < s) {
            float o = sm[threadIdx.x + s];
            sm[threadIdx.x] = isMin ? fminf(sm[threadIdx.x], o)
                                    : fmaxf(sm[threadIdx.x], o);
        }
        __syncthreads();
    }
    return sm[0];
}

__global__ void k_prep(const float* __restrict__ hv, int nh,
                       const float* __restrict__ ov, int no,
                       const int* __restrict__ faces, int F) {
    int t = threadIdx.x;
    float hmn[3] = { BIGF,  BIGF,  BIGF};
    float hmx[3] = {-BIGF, -BIGF, -BIGF};
    float omn[3] = { BIGF,  BIGF,  BIGF};
    float omx[3] = {-BIGF, -BIGF, -BIGF};
    for (int i = t; i < nh; i += 256) {
        #pragma unroll
        for (int c = 0; c < 3; c++) {
            float x = hv[i*3 + c];
            hmn[c] = fminf(hmn[c], x);
            hmx[c] = fmaxf(hmx[c], x);
        }
    }
    for (int i = t; i < no; i += 256) {
        #pragma unroll
        for (int c = 0; c < 3; c++) {
            float x = ov[i*3 + c];
            omn[c] = fminf(omn[c], x);
            omx[c] = fmaxf(omx[c], x);
        }
    }
    float bminh[3], bmaxh[3], bmino[3], bmaxo[3];
    #pragma unroll
    for (int c = 0; c < 3; c++) {
        bminh[c] = blockRed256(hmn[c], true);
        bmaxh[c] = blockRed256(hmx[c], false);
        bmino[c] = blockRed256(omn[c], true);
        bmaxo[c] = blockRed256(omx[c], false);
    }
    __shared__ float sp[4];
    if (t == 0) {
        float cx = __fmul_rn(0.5f, __fadd_rn(bminh[0], bmaxh[0]));
        float cy = __fmul_rn(0.5f, __fadd_rn(bminh[1], bmaxh[1]));
        float cz = __fmul_rn(0.5f, __fadd_rn(bminh[2], bmaxh[2]));
        float ext = fmaxf(fmaxf(__fsub_rn(bmaxh[0], bminh[0]),
                                __fsub_rn(bmaxh[1], bminh[1])),
                          __fsub_rn(bmaxh[2], bminh[2]));
        float scale = __fmul_rn(0.6f, ext);   // (1 + 0.2) * 0.5 exact in fp32
        bool ovl = true;
        #pragma unroll
        for (int c = 0; c < 3; c++) {
            ovl = ovl && (bminh[c] <= bmaxo[c]) && (bmino[c] <= bmaxh[c]);
        }
        g_params[0] = cx; g_params[1] = cy; g_params[2] = cz;
        g_params[3] = scale;
        g_params[4] = ovl ? 1.0f : 0.0f;
        sp[0] = cx; sp[1] = cy; sp[2] = cz; sp[3] = scale;
    }
    __syncthreads();
    float cx = sp[0], cy = sp[1], cz = sp[2], sc = sp[3];

    for (int f = t; f < F; f += 256) {
        int i0 = faces[f*3+0], i1 = faces[f*3+1], i2 = faces[f*3+2];
        float v0x = __fdiv_rn(__fsub_rn(hv[i0*3+0], cx), sc);
        float v0y = __fdiv_rn(__fsub_rn(hv[i0*3+1], cy), sc);
        float v0z = __fdiv_rn(__fsub_rn(hv[i0*3+2], cz), sc);
        float v1x = __fdiv_rn(__fsub_rn(hv[i1*3+0], cx), sc);
        float v1y = __fdiv_rn(__fsub_rn(hv[i1*3+1], cy), sc);
        float v1z = __fdiv_rn(__fsub_rn(hv[i1*3+2], cz), sc);
        float v2x = __fdiv_rn(__fsub_rn(hv[i2*3+0], cx), sc);
        float v2y = __fdiv_rn(__fsub_rn(hv[i2*3+1], cy), sc);
        float v2z = __fdiv_rn(__fsub_rn(hv[i2*3+2], cz), sc);
        float e0x = __fsub_rn(v1x, v0x), e0y = __fsub_rn(v1y, v0y), e0z = __fsub_rn(v1z, v0z);
        float e1x = __fsub_rn(v2x, v0x), e1y = __fsub_rn(v2y, v0y), e1z = __fsub_rn(v2z, v0z);
        float a = e0x*e0x + e0y*e0y + e0z*e0z;
        float b = e0x*e1x + e0y*e1y + e0z*e1z;
        float c = e1x*e1x + e1y*e1y + e1z*e1z;
        float det = a*c - b*b;
        bool detok = (det > EPSF);
        float invdet = 1.0f / (detok ? det : 1.0f);
        float inva = 1.0f / ((a > EPSF) ? a : 1.0f);
        float invc = 1.0f / ((c > EPSF) ? c : 1.0f);
        float ee2 = a + c - 2.0f*b;
        float invee2 = 1.0f / ((ee2 > EPSF) ? ee2 : 1.0f);
        float bma = b - a;
        // 2D projected determinant — exact-match path (no FMA contraction)
        float det2 = __fsub_rn(__fmul_rn(e0x, e1y), __fmul_rn(e1x, e0y));
        float ok2 = (fabsf(det2) > EPSF) ? 1.0f : 0.0f;
        float det2s = (fabsf(det2) > EPSF) ? det2 : 1.0f;

        g_face[F_V0X*MAXF+f] = v0x;  g_face[F_V0Y*MAXF+f] = v0y;  g_face[F_V0Z*MAXF+f] = v0z;
        g_face[F_E0X*MAXF+f] = e0x;  g_face[F_E0Y*MAXF+f] = e0y;  g_face[F_E0Z*MAXF+f] = e0z;
        g_face[F_E1X*MAXF+f] = e1x;  g_face[F_E1Y*MAXF+f] = e1y;  g_face[F_E1Z*MAXF+f] = e1z;
        g_face[F_A*MAXF+f] = a;      g_face[F_B*MAXF+f] = b;      g_face[F_C*MAXF+f] = c;
        g_face[F_INVA*MAXF+f] = inva;     g_face[F_INVC*MAXF+f] = invc;
        g_face[F_INVDET*MAXF+f] = invdet;
        g_face[F_DET*MAXF+f] = detok ? det : -BIGF;   // det' (detok folded)
        g_face[F_EE2*MAXF+f] = ee2;       g_face[F_INVEE2*MAXF+f] = invee2;
        g_face[F_BMA*MAXF+f] = bma;
        g_face[F_DET2S*MAXF+f] = det2s;   g_face[F_OK2*MAXF+f] = ok2;
    }
}

// ---------------- K2: phi grid (dominant kernel) ----------------
// 8 z-points per thread as 4 packed f32x2 pairs. Packed accumulators,
// clamp hoisted out of face loop, inside/outside select done arithmetically.
// grid: NSLICE*16 = 592 CTAs of 256 (= 2 full waves at 2 CTAs/SM).
__global__ __launch_bounds__(256, 2) void k_phi(int F) {
    const int FS = (F + NSLICE - 1) / NSLICE;
    int s = blockIdx.x >> 4;
    int t = ((blockIdx.x & 15) << 8) | threadIdx.x;  // [0, 4096)
    int x  = t & 31;
    int y  = (t >> 5) & 31;
    int zb = t >> 10;                                // 0..3

    float px = grid_coord(x);
    float py = grid_coord(y);
    float pzs[8];
    ull pz2[4];
    #pragma unroll
    for (int k = 0; k < 8; k++) pzs[k] = grid_coord(zb + 4*k);
    #pragma unroll
    for (int j = 0; j < 4; j++) pz2[j] = pack2(pzs[2*j], pzs[2*j+1]);

    ull acc2[4];
    int hits[8];
    #pragma unroll
    for (int j = 0; j < 4; j++) acc2[j] = pack2(BIGF, BIGF);
    #pragma unroll
    for (int k = 0; k < 8; k++) hits[k] = 0;

    __shared__ ull   spk[PK_N][FCHUNK];
    __shared__ float ssc[SC_N][FCHUNK];

    int fbeg = s * FS;
    int fend = min(F, fbeg + FS);
    for (int f0 = fbeg; f0 < fend; f0 += FCHUNK) {
        int nf = min(FCHUNK, fend - f0);
        __syncthreads();
        if (threadIdx.x < FCHUNK && threadIdx.x < (unsigned)nf) {
            int i = threadIdx.x;
            int f = f0 + i;
            float v0x = g_face[F_V0X*MAXF+f], v0y = g_face[F_V0Y*MAXF+f], v0z = g_face[F_V0Z*MAXF+f];
            float e0x = g_face[F_E0X*MAXF+f], e0y = g_face[F_E0Y*MAXF+f], e0z = g_face[F_E0Z*MAXF+f];
            float e1x = g_face[F_E1X*MAXF+f], e1y = g_face[F_E1Y*MAXF+f], e1z = g_face[F_E1Z*MAXF+f];
            float a = g_face[F_A*MAXF+f], b = g_face[F_B*MAXF+f], c = g_face[F_C*MAXF+f];
            float inva = g_face[F_INVA*MAXF+f], invc = g_face[F_INVC*MAXF+f];
            float invdet = g_face[F_INVDET*MAXF+f], detp = g_face[F_DET*MAXF+f];
            float ee2 = g_face[F_EE2*MAXF+f], invee2 = g_face[F_INVEE2*MAXF+f];
            float bma = g_face[F_BMA*MAXF+f];
            float det2s = g_face[F_DET2S*MAXF+f], ok2 = g_face[F_OK2*MAXF+f];

            spk[PK_NV0Z][i]    = pack2(-v0z, -v0z);
            spk[PK_E0Z][i]     = pack2(e0z, e0z);
            spk[PK_E1Z][i]     = pack2(e1z, e1z);
            spk[PK_A][i]       = pack2(a, a);
            spk[PK_NB][i]      = pack2(-b, -b);
            spk[PK_C][i]       = pack2(c, c);
            spk[PK_INVA][i]    = pack2(inva, inva);
            spk[PK_INVC][i]    = pack2(invc, invc);
            spk[PK_NINVDET][i] = pack2(-invdet, -invdet);
            spk[PK_EE2][i]     = pack2(ee2, ee2);
            spk[PK_INVEE2][i]  = pack2(invee2, invee2);
            float dz10 = e1z - e0z;
            spk[PK_DZ10][i]    = pack2(dz10, dz10);
            spk[PK_DETP][i]    = pack2(detp, detp);

            ssc[SC_V0X][i] = v0x;  ssc[SC_V0Y][i] = v0y;  ssc[SC_V0Z][i] = v0z;
            ssc[SC_E0X][i] = e0x;  ssc[SC_E0Y][i] = e0y;  ssc[SC_E0Z][i] = e0z;
            ssc[SC_E1X][i] = e1x;  ssc[SC_E1Y][i] = e1y;  ssc[SC_E1Z][i] = e1z;
            ssc[SC_DET2S][i] = det2s;  ssc[SC_OK2][i] = ok2;  ssc[SC_BMA][i] = bma;
        }
        __syncthreads();

        for (int j = 0; j < nf; j++) {
            float v0x = ssc[SC_V0X][j], v0y = ssc[SC_V0Y][j], v0z = ssc[SC_V0Z][j];
            float e0x = ssc[SC_E0X][j], e0y = ssc[SC_E0Y][j], e0z = ssc[SC_E0Z][j];
            float e1x = ssc[SC_E1X][j], e1y = ssc[SC_E1Y][j], e1z = ssc[SC_E1Z][j];
            float det2s = ssc[SC_DET2S][j], ok2 = ssc[SC_OK2][j], bma = ssc[SC_BMA][j];

            float wx = __fsub_rn(px, v0x);
            float wy = __fsub_rn(py, v0y);

            // --- ray cast: bit-matched to reference (IEEE div, no contraction) ---
            float nu = __fsub_rn(__fmul_rn(wx, e1y), __fmul_rn(wy, e1x));
            float nv = __fsub_rn(__fmul_rn(e0x, wy), __fmul_rn(e0y, wx));
            float u2 = __fdiv_rn(nu, det2s);
            float v2 = __fdiv_rn(nv, det2s);
            bool in2d = (u2 >= 0.0f) && (v2 >= 0.0f)
                     && (__fadd_rn(u2, v2) <= 1.0f) && (ok2 > 0.5f);
            float zint = __fadd_rn(__fadd_rn(v0z, __fmul_rn(u2, e0z)),
                                   __fmul_rn(v2, e1z));

            // --- distance bases (continuous path: rounding-tolerant) ---
            float s0  = wx*e0x + wy*e0y;
            float s1  = wx*e1x + wy*e1y;
            float fxy = wx*wx + wy*wy;
            float dot2b = s1 - s0 - bma;
            ull s02 = pack2(s0, s0);
            ull s12 = pack2(s1, s1);
            ull fxy2 = pack2(fxy, fxy);
            ull dot2b2 = pack2(dot2b, dot2b);

            ull nv0z2 = spk[PK_NV0Z][j];
            ull e0z2  = spk[PK_E0Z][j];
            ull e1z2  = spk[PK_E1Z][j];
            ull a2    = spk[PK_A][j];
            ull nb2   = spk[PK_NB][j];
            ull c2    = spk[PK_C][j];
            ull inva2 = spk[PK_INVA][j];
            ull invc2 = spk[PK_INVC][j];
            ull nivd2 = spk[PK_NINVDET][j];
            ull ee22  = spk[PK_EE2][j];
            ull ivee2 = spk[PK_INVEE2][j];
            ull dz102 = spk[PK_DZ10][j];
            ull detp2 = spk[PK_DETP][j];

            #pragma unroll
            for (int jp = 0; jp < 4; jp++) {
                ull wz2  = add2(pz2[jp], nv0z2);
                ull de02 = fma2(wz2, e0z2, s02);
                ull de12 = fma2(wz2, e1z2, s12);
                ull ff2  = fma2(wz2, wz2, fxy2);
                ull uN2  = fma2(nb2, de12, mul2(c2, de02));
                ull vN2  = fma2(nb2, de02, mul2(a2, de12));
                ull sum2 = add2(uN2, vN2);
                ull dterm = fma2(sum2, M1_2, detp2);          // det' - (uN+vN)
                // mask: == 0 iff inside triangle (and det ok); < 0 otherwise
                ull mask = min2(min2(uN2, vN2), min2(dterm, ZERO2));
                ull ps2 = fma2(vN2, de12, mul2(uN2, de02));
                ull plane2 = fma2(nivd2, ps2, ff2);
                ull plane_m = fma2(mask, NEGBIG2, plane2);    // +huge when outside
                ull m2de0 = mul2(de02, MTWO2);
                ull t02 = min2(max2(mul2(de02, inva2), ZERO2), ONE2);
                ull d02 = fma2(t02, fma2(t02, a2, m2de0), ff2);
                ull m2de1 = mul2(de12, MTWO2);
                ull t12 = min2(max2(mul2(de12, invc2), ZERO2), ONE2);
                ull d12 = fma2(t12, fma2(t12, c2, m2de1), ff2);
                ull dot22 = fma2(wz2, dz102, dot2b2);
                ull w1sq2 = add2(add2(ff2, a2), m2de0);
                ull t22 = min2(max2(mul2(dot22, ivee2), ZERO2), ONE2);
                ull d222 = fma2(t22, fma2(t22, ee22, mul2(dot22, MTWO2)), w1sq2);
                ull ed2 = min2(min2(d02, d12), d222);
                acc2[jp] = min2(acc2[jp], min2(ed2, plane_m));
                hits[2*jp]   += (in2d && (zint > pzs[2*jp]))   ? 1 : 0;
                hits[2*jp+1] += (in2d && (zint > pzs[2*jp+1])) ? 1 : 0;
            }
        }
    }

    #pragma unroll
    for (int jp = 0; jp < 4; jp++) {
        float dlo, dhi;
        unpack2(dlo, dhi, acc2[jp]);
        dlo = fmaxf(dlo, 0.0f);    // clamp commutes with min: hoisted here
        dhi = fmaxf(dhi, 0.0f);
        int zlo = zb + 4*(2*jp);
        int zhi = zb + 4*(2*jp+1);
        int nlo = ((zlo << 5) | y) * 32 + x;
        int nhi = ((zhi << 5) | y) * 32 + x;
        g_slice[s * NPTS + nlo] = make_uint2(__float_as_uint(dlo), (unsigned)hits[2*jp]);
        g_slice[s * NPTS + nhi] = make_uint2(__float_as_uint(dhi), (unsigned)hits[2*jp+1]);
    }
}

// ---------------- K3: combine slices -> phi ----------------
__global__ void k_combine() {
    int n = blockIdx.x * 256 + threadIdx.x;
    unsigned db = __float_as_uint(BIGF);
    int h = 0;
    #pragma unroll
    for (int s = 0; s < NSLICE; s++) {
        uint2 v = g_slice[s * NPTS + n];
        db = min(db, v.x);          // d2 >= 0 -> uint order == float order
        h += (int)v.y;
    }
    g_phi[n] = __fsqrt_rn(__uint_as_float(db)) * ((h & 1) ? 1.0f : 0.0f);
}

// ---------------- K4: trilinear sample -> partial sums (8 CTAs) ----------------
__global__ void k_lossp(const float* __restrict__ ov, int no) {
    __shared__ float red[512];
    int t = threadIdx.x;
    float cx = g_params[0], cy = g_params[1], cz = g_params[2];
    float sc = g_params[3];
    float acc = 0.0f;
    for (int i = blockIdx.x * 512 + t; i < no; i += 8 * 512) {
        float qx = __fdiv_rn(__fsub_rn(ov[i*3+0], cx), sc);
        float qy = __fdiv_rn(__fsub_rn(ov[i*3+1], cy), sc);
        float qz = __fdiv_rn(__fsub_rn(ov[i*3+2], cz), sc);
        float fx = __fmul_rn(__fmul_rn(__fadd_rn(qx, 1.0f), 0.5f), (float)(G - 1));
        float fy = __fmul_rn(__fmul_rn(__fadd_rn(qy, 1.0f), 0.5f), (float)(G - 1));
        float fz = __fmul_rn(__fmul_rn(__fadd_rn(qz, 1.0f), 0.5f), (float)(G - 1));
        float flx = floorf(fx), fly = floorf(fy), flz = floorf(fz);
        int ix0 = (int)flx, iy0 = (int)fly, iz0 = (int)flz;
        float wx1 = __fsub_rn(fx, flx), wy1 = __fsub_rn(fy, fly), wz1 = __fsub_rn(fz, flz);
        float wx0 = __fsub_rn(1.0f, wx1), wy0 = __fsub_rn(1.0f, wy1), wz0 = __fsub_rn(1.0f, wz1);
        float val = 0.0f;
        #pragma unroll
        for (int dz = 0; dz < 2; dz++) {
            #pragma unroll
            for (int dy = 0; dy < 2; dy++) {
                #pragma unroll
                for (int dx = 0; dx < 2; dx++) {
                    int ix = ix0 + dx, iy = iy0 + dy, iz = iz0 + dz;
                    bool valid = (ix >= 0) && (ix < G) && (iy >= 0) && (iy < G)
                              && (iz >= 0) && (iz < G);
                    int cix = min(max(ix, 0), G-1);
                    int ciy = min(max(iy, 0), G-1);
                    int ciz = min(max(iz, 0), G-1);
                    float pv = g_phi[(ciz * G + ciy) * G + cix];
                    float w = __fmul_rn(__fmul_rn(dx ? wx1 : wx0, dy ? wy1 : wy0),
                                        dz ? wz1 : wz0);
                    val = __fadd_rn(val, valid ? __fmul_rn(pv, w) : 0.0f);
                }
            }
        }
        acc += val;
    }
    red[t] = acc;
    __syncthreads();
    for (int s = 256; s > 0; s >>= 1) {
        if (t < s) red[t] += red[t + s];
        __syncthreads();
    }
    if (t == 0) g_lpart[blockIdx.x] = red[0];
}

// ---------------- K5: final ----------------
__global__ void k_final(float* __restrict__ out) {
    float sum = 0.0f;
    #pragma unroll
    for (int i = 0; i < 8; i++) sum += g_lpart[i];
    float loss = __fmul_rn(sum, sum);
    out[0] = (g_params[4] > 0.5f) ? loss : 0.0f;
}

// ---------------- launch ----------------
extern "C" void kernel_launch(void* const* d_in, const int* in_sizes, int n_in,
                              void* d_out, int out_size) {
    const float* hv    = (const float*)d_in[0];
    const float* ov    = (const float*)d_in[1];
    const int*   faces = (const int*)d_in[2];
    int nh = in_sizes[0] / 3;
    int no = in_sizes[1] / 3;
    int F  = in_sizes[2] / 3;
    if (F > MAXF) F = MAXF;

    k_prep<<<1, 256>>>(hv, nh, ov, no, faces, F);
    k_phi<<<NSLICE * 16, 256>>>(F);
    k_combine<<<NPTS / 256, 256>>>();
    k_lossp<<<8, 512>>>(ov, no);
    k_final<<<1, 32>>>((float*)d_out);
}

// round 5
// speedup vs baseline: 1.2908x; 1.0700x over previous
#include <cuda_runtime.h>
#include <math.h>

#define G 32
#define NPTS (G*G*G)
#define MAXF 2048
#define NSLICE 37
#define FCHUNK 64
#define REC 9                    // float4s per face record
#define EPSF 1e-12f
#define BIGF 1e30f

typedef unsigned long long ull;

// ---------------- packed f32x2 helpers (sm_103a: only fma/mul/add exist) ----
__device__ __forceinline__ ull fma2(ull a, ull b, ull c) {
    ull d; asm("fma.rn.f32x2 %0, %1, %2, %3;" : "=l"(d) : "l"(a), "l"(b), "l"(c)); return d;
}
__device__ __forceinline__ ull mul2(ull a, ull b) {
    ull d; asm("mul.rn.f32x2 %0, %1, %2;" : "=l"(d) : "l"(a), "l"(b)); return d;
}
__device__ __forceinline__ ull add2(ull a, ull b) {
    ull d; asm("add.rn.f32x2 %0, %1, %2;" : "=l"(d) : "l"(a), "l"(b)); return d;
}
__device__ __forceinline__ ull pack2(float lo, float hi) {
    ull d; asm("mov.b64 %0, {%1, %2};" : "=l"(d) : "f"(lo), "f"(hi)); return d;
}
__device__ __forceinline__ void unpack2(float& lo, float& hi, ull v) {
    asm("mov.b64 {%0, %1}, %2;" : "=f"(lo), "=f"(hi) : "l"(v));
}
// emulated packed min/max: 2x FMNMX on the register-pair halves
__device__ __forceinline__ ull min2(ull a, ull b) {
    float al, ah, bl, bh;
    unpack2(al, ah, a); unpack2(bl, bh, b);
    return pack2(fminf(al, bl), fminf(ah, bh));
}
__device__ __forceinline__ ull max2(ull a, ull b) {
    float al, ah, bl, bh;
    unpack2(al, ah, a); unpack2(bl, bh, b);
    return pack2(fmaxf(al, bl), fmaxf(ah, bh));
}

#define ONE2    0x3F8000003F800000ULL
#define M1_2    0xBF800000BF800000ULL
#define MTWO2   0xC0000000C0000000ULL
#define ZERO2   0ULL
#define NEGBIG2 0xF149F2CAF149F2CAULL   // (-1e30f, -1e30f)

// ---------------- device scratch ----------------
__device__ float  g_params[8];               // cx, cy, cz, scale, overlap
__device__ float4 g_face4[MAXF * REC];       // AoS per-face records (144B each)
__device__ uint2  g_slice[NSLICE * NPTS];    // (d2 bits, hits) per slice per point
__device__ float  g_phi[NPTS];               // phi grid [z,y,x]
__device__ float  g_lpart[32];               // loss partial sums

__device__ __forceinline__ float grid_coord(int i) {
    const float step = 2.0f / 31.0f;
    if (i == G - 1) return 1.0f;
    return __fadd_rn(-1.0f, __fmul_rn((float)i, step));
}

// ---------------- K1: bboxes -> center/scale/overlap ----------------
__device__ __forceinline__ float blockRed256(float v, bool isMin) {
    __shared__ float sm[256];
    __syncthreads();
    sm[threadIdx.x] = v;
    __syncthreads();
    for (int s = 128; s > 0; s >>= 1) {
        if (threadIdx.x < s) {
            float o = sm[threadIdx.x + s];
            sm[threadIdx.x] = isMin ? fminf(sm[threadIdx.x], o)
                                    : fmaxf(sm[threadIdx.x], o);
        }
        __syncthreads();
    }
    return sm[0];
}

__global__ void k_bbox(const float* __restrict__ hv, int nh,
                       const float* __restrict__ ov, int no) {
    int t = threadIdx.x;
    float hmn[3] = { BIGF,  BIGF,  BIGF};
    float hmx[3] = {-BIGF, -BIGF, -BIGF};
    float omn[3] = { BIGF,  BIGF,  BIGF};
    float omx[3] = {-BIGF, -BIGF, -BIGF};
    for (int i = t; i < nh; i += 256) {
        #pragma unroll
        for (int c = 0; c < 3; c++) {
            float x = hv[i*3 + c];
            hmn[c] = fminf(hmn[c], x);
            hmx[c] = fmaxf(hmx[c], x);
        }
    }
    for (int i = t; i < no; i += 256) {
        #pragma unroll
        for (int c = 0; c < 3; c++) {
            float x = ov[i*3 + c];
            omn[c] = fminf(omn[c], x);
            omx[c] = fmaxf(omx[c], x);
        }
    }
    float bminh[3], bmaxh[3], bmino[3], bmaxo[3];
    #pragma unroll
    for (int c = 0; c < 3; c++) {
        bminh[c] = blockRed256(hmn[c], true);
        bmaxh[c] = blockRed256(hmx[c], false);
        bmino[c] = blockRed256(omn[c], true);
        bmaxo[c] = blockRed256(omx[c], false);
    }
    if (t == 0) {
        float cx = __fmul_rn(0.5f, __fadd_rn(bminh[0], bmaxh[0]));
        float cy = __fmul_rn(0.5f, __fadd_rn(bminh[1], bmaxh[1]));
        float cz = __fmul_rn(0.5f, __fadd_rn(bminh[2], bmaxh[2]));
        float ext = fmaxf(fmaxf(__fsub_rn(bmaxh[0], bminh[0]),
                                __fsub_rn(bmaxh[1], bminh[1])),
                          __fsub_rn(bmaxh[2], bminh[2]));
        float scale = __fmul_rn(0.6f, ext);   // (1 + 0.2) * 0.5 exact in fp32
        bool ovl = true;
        #pragma unroll
        for (int c = 0; c < 3; c++) {
            ovl = ovl && (bminh[c] <= bmaxo[c]) && (bmino[c] <= bmaxh[c]);
        }
        g_params[0] = cx; g_params[1] = cy; g_params[2] = cz;
        g_params[3] = scale;
        g_params[4] = ovl ? 1.0f : 0.0f;
    }
}

// ---------------- K2: per-face precompute -> AoS records ----------------
__global__ void k_faces(const float* __restrict__ hv,
                        const int* __restrict__ faces, int F) {
    int f = blockIdx.x * blockDim.x + threadIdx.x;
    if (f >= F) return;
    float cx = g_params[0], cy = g_params[1], cz = g_params[2];
    float sc = g_params[3];
    int i0 = faces[f*3+0], i1 = faces[f*3+1], i2 = faces[f*3+2];
    float v0x = __fdiv_rn(__fsub_rn(hv[i0*3+0], cx), sc);
    float v0y = __fdiv_rn(__fsub_rn(hv[i0*3+1], cy), sc);
    float v0z = __fdiv_rn(__fsub_rn(hv[i0*3+2], cz), sc);
    float v1x = __fdiv_rn(__fsub_rn(hv[i1*3+0], cx), sc);
    float v1y = __fdiv_rn(__fsub_rn(hv[i1*3+1], cy), sc);
    float v1z = __fdiv_rn(__fsub_rn(hv[i1*3+2], cz), sc);
    float v2x = __fdiv_rn(__fsub_rn(hv[i2*3+0], cx), sc);
    float v2y = __fdiv_rn(__fsub_rn(hv[i2*3+1], cy), sc);
    float v2z = __fdiv_rn(__fsub_rn(hv[i2*3+2], cz), sc);
    float e0x = __fsub_rn(v1x, v0x), e0y = __fsub_rn(v1y, v0y), e0z = __fsub_rn(v1z, v0z);
    float e1x = __fsub_rn(v2x, v0x), e1y = __fsub_rn(v2y, v0y), e1z = __fsub_rn(v2z, v0z);
    float a = e0x*e0x + e0y*e0y + e0z*e0z;
    float b = e0x*e1x + e0y*e1y + e0z*e1z;
    float c = e1x*e1x + e1y*e1y + e1z*e1z;
    float det = a*c - b*b;
    bool detok = (det > EPSF);
    float invdet = 1.0f / (detok ? det : 1.0f);
    float inva = 1.0f / ((a > EPSF) ? a : 1.0f);
    float invc = 1.0f / ((c > EPSF) ? c : 1.0f);
    float ee2 = a + c - 2.0f*b;
    float invee2 = 1.0f / ((ee2 > EPSF) ? ee2 : 1.0f);
    float bma = b - a;
    float detp = detok ? det : -BIGF;
    float dz10 = e1z - e0z;
    // 2D projected determinant — exact-match path (no FMA contraction)
    float det2 = __fsub_rn(__fmul_rn(e0x, e1y), __fmul_rn(e1x, e0y));
    float ok2 = (fabsf(det2) > EPSF) ? 1.0f : 0.0f;
    float det2s = (fabsf(det2) > EPSF) ? det2 : 1.0f;

    float4* r = &g_face4[f * REC];
    r[0] = make_float4(-v0z, -v0z, e0z, e0z);
    r[1] = make_float4(e1z, e1z, a, a);
    r[2] = make_float4(-b, -b, c, c);
    r[3] = make_float4(inva, inva, invc, invc);
    r[4] = make_float4(-invdet, -invdet, ee2, ee2);
    r[5] = make_float4(invee2, invee2, dz10, dz10);
    r[6] = make_float4(detp, detp, v0z, bma);
    r[7] = make_float4(v0x, v0y, e0x, e0y);
    r[8] = make_float4(e1x, e1y, det2s, ok2);
}

// ---------------- K3: phi grid (dominant kernel) ----------------
// 8 z-points per thread as 4 packed f32x2 pairs, AoS face records (9 LDS.128
// per face), face loop unrolled x2.
// grid: NSLICE*16 = 592 CTAs of 256 (= 2 full waves at 2 CTAs/SM).
__global__ __launch_bounds__(256, 2) void k_phi(int F) {
    const int FS = (F + NSLICE - 1) / NSLICE;
    int s = blockIdx.x >> 4;
    int t = ((blockIdx.x & 15) << 8) | threadIdx.x;  // [0, 4096)
    int x  = t & 31;
    int y  = (t >> 5) & 31;
    int zb = t >> 10;                                // 0..3

    float px = grid_coord(x);
    float py = grid_coord(y);
    float pzs[8];
    ull pz2[4];
    #pragma unroll
    for (int k = 0; k < 8; k++) pzs[k] = grid_coord(zb + 4*k);
    #pragma unroll
    for (int j = 0; j < 4; j++) pz2[j] = pack2(pzs[2*j], pzs[2*j+1]);

    ull acc2[4];
    int hits[8];
    #pragma unroll
    for (int j = 0; j < 4; j++) acc2[j] = pack2(BIGF, BIGF);
    #pragma unroll
    for (int k = 0; k < 8; k++) hits[k] = 0;

    __shared__ float4 sf4[FCHUNK * REC];

    int fbeg = s * FS;
    int fend = min(F, fbeg + FS);
    for (int f0 = fbeg; f0 < fend; f0 += FCHUNK) {
        int nf = min(FCHUNK, fend - f0);
        __syncthreads();
        for (int i = threadIdx.x; i < nf * REC; i += 256)
            sf4[i] = g_face4[f0 * REC + i];
        __syncthreads();

        #pragma unroll 2
        for (int j = 0; j < nf; j++) {
            const float4* r = &sf4[j * REC];
            float4 q0 = r[0], q1 = r[1], q2 = r[2], q3 = r[3], q4 = r[4];
            float4 q5 = r[5], q6 = r[6], q7 = r[7], q8 = r[8];

            float v0x = q7.x, v0y = q7.y, e0x = q7.z, e0y = q7.w;
            float e1x = q8.x, e1y = q8.y, det2s = q8.z, ok2 = q8.w;
            float v0z = q6.z, bma = q6.w;
            float e0z = q0.z, e1z = q1.x;

            float wx = __fsub_rn(px, v0x);
            float wy = __fsub_rn(py, v0y);

            // --- ray cast: bit-matched to reference (IEEE div, no contraction) ---
            float nu = __fsub_rn(__fmul_rn(wx, e1y), __fmul_rn(wy, e1x));
            float nv = __fsub_rn(__fmul_rn(e0x, wy), __fmul_rn(e0y, wx));
            float u2 = __fdiv_rn(nu, det2s);
            float v2 = __fdiv_rn(nv, det2s);
            bool in2d = (u2 >= 0.0f) && (v2 >= 0.0f)
                     && (__fadd_rn(u2, v2) <= 1.0f) && (ok2 > 0.5f);
            float zint = __fadd_rn(__fadd_rn(v0z, __fmul_rn(u2, e0z)),
                                   __fmul_rn(v2, e1z));

            // --- distance bases (continuous path: rounding-tolerant) ---
            float s0  = wx*e0x + wy*e0y;
            float s1  = wx*e1x + wy*e1y;
            float fxy = wx*wx + wy*wy;
            float dot2b = s1 - s0 - bma;
            ull s02 = pack2(s0, s0);
            ull s12 = pack2(s1, s1);
            ull fxy2 = pack2(fxy, fxy);
            ull dot2b2 = pack2(dot2b, dot2b);

            ull nv0z2 = pack2(q0.x, q0.y);
            ull e0z2  = pack2(q0.z, q0.w);
            ull e1z2  = pack2(q1.x, q1.y);
            ull a2    = pack2(q1.z, q1.w);
            ull nb2   = pack2(q2.x, q2.y);
            ull c2    = pack2(q2.z, q2.w);
            ull inva2 = pack2(q3.x, q3.y);
            ull invc2 = pack2(q3.z, q3.w);
            ull nivd2 = pack2(q4.x, q4.y);
            ull ee22  = pack2(q4.z, q4.w);
            ull ivee2 = pack2(q5.x, q5.y);
            ull dz102 = pack2(q5.z, q5.w);
            ull detp2 = pack2(q6.x, q6.y);

            #pragma unroll
            for (int jp = 0; jp < 4; jp++) {
                ull wz2  = add2(pz2[jp], nv0z2);
                ull de02 = fma2(wz2, e0z2, s02);
                ull de12 = fma2(wz2, e1z2, s12);
                ull ff2  = fma2(wz2, wz2, fxy2);
                ull uN2  = fma2(nb2, de12, mul2(c2, de02));
                ull vN2  = fma2(nb2, de02, mul2(a2, de12));
                ull sum2 = add2(uN2, vN2);
                ull dterm = fma2(sum2, M1_2, detp2);          // det' - (uN+vN)
                // mask: == 0 iff inside triangle (and det ok); < 0 otherwise
                ull mask = min2(min2(uN2, vN2), min2(dterm, ZERO2));
                ull ps2 = fma2(vN2, de12, mul2(uN2, de02));
                ull plane2 = fma2(nivd2, ps2, ff2);
                ull plane_m = fma2(mask, NEGBIG2, plane2);    // +huge when outside
                ull m2de0 = mul2(de02, MTWO2);
                ull t02 = min2(max2(mul2(de02, inva2), ZERO2), ONE2);
                ull d02 = fma2(t02, fma2(t02, a2, m2de0), ff2);
                ull m2de1 = mul2(de12, MTWO2);
                ull t12 = min2(max2(mul2(de12, invc2), ZERO2), ONE2);
                ull d12 = fma2(t12, fma2(t12, c2, m2de1), ff2);
                ull dot22 = fma2(wz2, dz102, dot2b2);
                ull w1sq2 = add2(add2(ff2, a2), m2de0);
                ull t22 = min2(max2(mul2(dot22, ivee2), ZERO2), ONE2);
                ull d222 = fma2(t22, fma2(t22, ee22, mul2(dot22, MTWO2)), w1sq2);
                ull ed2 = min2(min2(d02, d12), d222);
                acc2[jp] = min2(acc2[jp], min2(ed2, plane_m));
                hits[2*jp]   += (in2d && (zint > pzs[2*jp]))   ? 1 : 0;
                hits[2*jp+1] += (in2d && (zint > pzs[2*jp+1])) ? 1 : 0;
            }
        }
    }

    #pragma unroll
    for (int jp = 0; jp < 4; jp++) {
        float dlo, dhi;
        unpack2(dlo, dhi, acc2[jp]);
        dlo = fmaxf(dlo, 0.0f);    // clamp commutes with min: hoisted here
        dhi = fmaxf(dhi, 0.0f);
        int zlo = zb + 4*(2*jp);
        int zhi = zb + 4*(2*jp+1);
        int nlo = ((zlo << 5) | y) * 32 + x;
        int nhi = ((zhi << 5) | y) * 32 + x;
        g_slice[s * NPTS + nlo] = make_uint2(__float_as_uint(dlo), (unsigned)hits[2*jp]);
        g_slice[s * NPTS + nhi] = make_uint2(__float_as_uint(dhi), (unsigned)hits[2*jp+1]);
    }
}

// ---------------- K4: combine slices -> phi ----------------
__global__ void k_combine() {
    int n = blockIdx.x * 256 + threadIdx.x;
    unsigned db = __float_as_uint(BIGF);
    int h = 0;
    #pragma unroll
    for (int s = 0; s < NSLICE; s++) {
        uint2 v = g_slice[s * NPTS + n];
        db = min(db, v.x);          // d2 >= 0 -> uint order == float order
        h += (int)v.y;
    }
    g_phi[n] = __fsqrt_rn(__uint_as_float(db)) * ((h & 1) ? 1.0f : 0.0f);
}

// ---------------- K5: trilinear sample -> partial sums (32 CTAs x 128) -------
__global__ void k_lossp(const float* __restrict__ ov, int no) {
    __shared__ float wsum[4];
    int t = threadIdx.x;
    float cx = g_params[0], cy = g_params[1], cz = g_params[2];
    float sc = g_params[3];
    float acc = 0.0f;
    for (int i = blockIdx.x * 128 + t; i < no; i += 32 * 128) {
        float qx = __fdiv_rn(__fsub_rn(ov[i*3+0], cx), sc);
        float qy = __fdiv_rn(__fsub_rn(ov[i*3+1], cy), sc);
        float qz = __fdiv_rn(__fsub_rn(ov[i*3+2], cz), sc);
        float fx = __fmul_rn(__fmul_rn(__fadd_rn(qx, 1.0f), 0.5f), (float)(G - 1));
        float fy = __fmul_rn(__fmul_rn(__fadd_rn(qy, 1.0f), 0.5f), (float)(G - 1));
        float fz = __fmul_rn(__fmul_rn(__fadd_rn(qz, 1.0f), 0.5f), (float)(G - 1));
        float flx = floorf(fx), fly = floorf(fy), flz = floorf(fz);
        int ix0 = (int)flx, iy0 = (int)fly, iz0 = (int)flz;
        float wx1 = __fsub_rn(fx, flx), wy1 = __fsub_rn(fy, fly), wz1 = __fsub_rn(fz, flz);
        float wx0 = __fsub_rn(1.0f, wx1), wy0 = __fsub_rn(1.0f, wy1), wz0 = __fsub_rn(1.0f, wz1);
        float val = 0.0f;
        #pragma unroll
        for (int dz = 0; dz < 2; dz++) {
            #pragma unroll
            for (int dy = 0; dy < 2; dy++) {
                #pragma unroll
                for (int dx = 0; dx < 2; dx++) {
                    int ix = ix0 + dx, iy = iy0 + dy, iz = iz0 + dz;
                    bool valid = (ix >= 0) && (ix < G) && (iy >= 0) && (iy < G)
                              && (iz >= 0) && (iz < G);
                    int cix = min(max(ix, 0), G-1);
                    int ciy = min(max(iy, 0), G-1);
                    int ciz = min(max(iz, 0), G-1);
                    float pv = g_phi[(ciz * G + ciy) * G + cix];
                    float w = __fmul_rn(__fmul_rn(dx ? wx1 : wx0, dy ? wy1 : wy0),
                                        dz ? wz1 : wz0);
                    val = __fadd_rn(val, valid ? __fmul_rn(pv, w) : 0.0f);
                }
            }
        }
        acc += val;
    }
    // warp reduce (fixed order)
    #pragma unroll
    for (int o = 16; o > 0; o >>= 1)
        acc += __shfl_down_sync(0xFFFFFFFFu, acc, o);
    if ((t & 31) == 0) wsum[t >> 5] = acc;
    __syncthreads();
    if (t == 0)
        g_lpart[blockIdx.x] = ((wsum[0] + wsum[1]) + wsum[2]) + wsum[3];
}

// ---------------- K6: final ----------------
__global__ void k_final(float* __restrict__ out) {
    if (threadIdx.x == 0) {
        float sum = 0.0f;
        #pragma unroll
        for (int i = 0; i < 32; i++) sum += g_lpart[i];
        float loss = __fmul_rn(sum, sum);
        out[0] = (g_params[4] > 0.5f) ? loss : 0.0f;
    }
}

// ---------------- launch ----------------
extern "C" void kernel_launch(void* const* d_in, const int* in_sizes, int n_in,
                              void* d_out, int out_size) {
    const float* hv    = (const float*)d_in[0];
    const float* ov    = (const float*)d_in[1];
    const int*   faces = (const int*)d_in[2];
    int nh = in_sizes[0] / 3;
    int no = in_sizes[1] / 3;
    int F  = in_sizes[2] / 3;
    if (F > MAXF) F = MAXF;

    k_bbox<<<1, 256>>>(hv, nh, ov, no);
    k_faces<<<(F + 127) / 128, 128>>>(hv, faces, F);
    k_phi<<<NSLICE * 16, 256>>>(F);
    k_combine<<<NPTS / 256, 256>>>();
    k_lossp<<<32, 128>>>(ov, no);
    k_final<<<1, 32>>>((float*)d_out);
}

// round 6
// speedup vs baseline: 1.4017x; 1.0859x over previous
#include <cuda_runtime.h>
#include <math.h>

#define G 32
#define NPTS (G*G*G)
#define NXY (G*G)
#define MAXF 2048
#define NSLICE 37
#define FCHUNK 64
#define REC 9                    // float4s per face record
#define EPSF 1e-12f
#define BIGF 1e30f

typedef unsigned long long ull;

// ---------------- packed f32x2 helpers (sm_103a: only fma/mul/add exist) ----
__device__ __forceinline__ ull fma2(ull a, ull b, ull c) {
    ull d; asm("fma.rn.f32x2 %0, %1, %2, %3;" : "=l"(d) : "l"(a), "l"(b), "l"(c)); return d;
}
__device__ __forceinline__ ull mul2(ull a, ull b) {
    ull d; asm("mul.rn.f32x2 %0, %1, %2;" : "=l"(d) : "l"(a), "l"(b)); return d;
}
__device__ __forceinline__ ull add2(ull a, ull b) {
    ull d; asm("add.rn.f32x2 %0, %1, %2;" : "=l"(d) : "l"(a), "l"(b)); return d;
}
__device__ __forceinline__ ull pack2(float lo, float hi) {
    ull d; asm("mov.b64 %0, {%1, %2};" : "=l"(d) : "f"(lo), "f"(hi)); return d;
}
__device__ __forceinline__ void unpack2(float& lo, float& hi, ull v) {
    asm("mov.b64 {%0, %1}, %2;" : "=f"(lo), "=f"(hi) : "l"(v));
}
// emulated packed min/max: 2x FMNMX on the register-pair halves
__device__ __forceinline__ ull min2(ull a, ull b) {
    float al, ah, bl, bh;
    unpack2(al, ah, a); unpack2(bl, bh, b);
    return pack2(fminf(al, bl), fminf(ah, bh));
}
__device__ __forceinline__ ull max2(ull a, ull b) {
    float al, ah, bl, bh;
    unpack2(al, ah, a); unpack2(bl, bh, b);
    return pack2(fmaxf(al, bl), fmaxf(ah, bh));
}

#define ONE2    0x3F8000003F800000ULL
#define MTWO2   0xC0000000C0000000ULL
#define ZERO2   0ULL
#define NEGBIG2 0xF149F2CAF149F2CAULL   // (-1e30f, -1e30f)

// ---------------- device scratch ----------------
__device__ float    g_params[8];                 // cx, cy, cz, scale, overlap
__device__ float4   g_face4[MAXF * REC];         // AoS per-face records (144B)
__device__ float    g_d2[NSLICE * NPTS];         // per-slice min squared dist
__device__ unsigned g_par[NSLICE * 2 * NXY];     // per-slice 16-bit z parities
__device__ float    g_phi[NPTS];                 // phi grid [z,y,x]
__device__ float    g_lpart[32];                 // loss partial sums

__device__ __forceinline__ float grid_coord(int i) {
    // jnp.linspace(-1, 1, 32): start + iota*delta, endpoint exact
    const float step = 2.0f / 31.0f;
    if (i == G - 1) return 1.0f;
    return __fadd_rn(-1.0f, __fmul_rn((float)i, step));
}

// ---------------- K1: bboxes -> center/scale/overlap ----------------
__device__ __forceinline__ float blockRed256(float v, bool isMin) {
    __shared__ float sm[256];
    __syncthreads();
    sm[threadIdx.x] = v;
    __syncthreads();
    for (int s = 128; s > 0; s >>= 1) {
        if (threadIdx.x < s) {
            float o = sm[threadIdx.x + s];
            sm[threadIdx.x] = isMin ? fminf(sm[threadIdx.x], o)
                                    : fmaxf(sm[threadIdx.x], o);
        }
        __syncthreads();
    }
    return sm[0];
}

__global__ void k_bbox(const float* __restrict__ hv, int nh,
                       const float* __restrict__ ov, int no) {
    int t = threadIdx.x;
    float hmn[3] = { BIGF,  BIGF,  BIGF};
    float hmx[3] = {-BIGF, -BIGF, -BIGF};
    float omn[3] = { BIGF,  BIGF,  BIGF};
    float omx[3] = {-BIGF, -BIGF, -BIGF};
    for (int i = t; i < nh; i += 256) {
        #pragma unroll
        for (int c = 0; c < 3; c++) {
            float x = hv[i*3 + c];
            hmn[c] = fminf(hmn[c], x);
            hmx[c] = fmaxf(hmx[c], x);
        }
    }
    for (int i = t; i < no; i += 256) {
        #pragma unroll
        for (int c = 0; c < 3; c++) {
            float x = ov[i*3 + c];
            omn[c] = fminf(omn[c], x);
            omx[c] = fmaxf(omx[c], x);
        }
    }
    float bminh[3], bmaxh[3], bmino[3], bmaxo[3];
    #pragma unroll
    for (int c = 0; c < 3; c++) {
        bminh[c] = blockRed256(hmn[c], true);
        bmaxh[c] = blockRed256(hmx[c], false);
        bmino[c] = blockRed256(omn[c], true);
        bmaxo[c] = blockRed256(omx[c], false);
    }
    if (t == 0) {
        float cx = __fmul_rn(0.5f, __fadd_rn(bminh[0], bmaxh[0]));
        float cy = __fmul_rn(0.5f, __fadd_rn(bminh[1], bmaxh[1]));
        float cz = __fmul_rn(0.5f, __fadd_rn(bminh[2], bmaxh[2]));
        float ext = fmaxf(fmaxf(__fsub_rn(bmaxh[0], bminh[0]),
                                __fsub_rn(bmaxh[1], bminh[1])),
                          __fsub_rn(bmaxh[2], bminh[2]));
        float scale = __fmul_rn(0.6f, ext);   // (1 + 0.2) * 0.5 exact in fp32
        bool ovl = true;
        #pragma unroll
        for (int c = 0; c < 3; c++) {
            ovl = ovl && (bminh[c] <= bmaxo[c]) && (bmino[c] <= bmaxh[c]);
        }
        g_params[0] = cx; g_params[1] = cy; g_params[2] = cz;
        g_params[3] = scale;
        g_params[4] = ovl ? 1.0f : 0.0f;
    }
}

// ---------------- K2: per-face precompute -> AoS records ----------------
__global__ void k_faces(const float* __restrict__ hv,
                        const int* __restrict__ faces, int F) {
    int f = blockIdx.x * blockDim.x + threadIdx.x;
    if (f >= F) return;
    float cx = g_params[0], cy = g_params[1], cz = g_params[2];
    float sc = g_params[3];
    int i0 = faces[f*3+0], i1 = faces[f*3+1], i2 = faces[f*3+2];
    float v0x = __fdiv_rn(__fsub_rn(hv[i0*3+0], cx), sc);
    float v0y = __fdiv_rn(__fsub_rn(hv[i0*3+1], cy), sc);
    float v0z = __fdiv_rn(__fsub_rn(hv[i0*3+2], cz), sc);
    float v1x = __fdiv_rn(__fsub_rn(hv[i1*3+0], cx), sc);
    float v1y = __fdiv_rn(__fsub_rn(hv[i1*3+1], cy), sc);
    float v1z = __fdiv_rn(__fsub_rn(hv[i1*3+2], cz), sc);
    float v2x = __fdiv_rn(__fsub_rn(hv[i2*3+0], cx), sc);
    float v2y = __fdiv_rn(__fsub_rn(hv[i2*3+1], cy), sc);
    float v2z = __fdiv_rn(__fsub_rn(hv[i2*3+2], cz), sc);
    float e0x = __fsub_rn(v1x, v0x), e0y = __fsub_rn(v1y, v0y), e0z = __fsub_rn(v1z, v0z);
    float e1x = __fsub_rn(v2x, v0x), e1y = __fsub_rn(v2y, v0y), e1z = __fsub_rn(v2z, v0z);
    float a = e0x*e0x + e0y*e0y + e0z*e0z;
    float b = e0x*e1x + e0y*e1y + e0z*e1z;
    float c = e1x*e1x + e1y*e1y + e1z*e1z;
    float det = a*c - b*b;
    bool detok = (det > EPSF);
    float invdet = 1.0f / (detok ? det : 1.0f);
    float inva = 1.0f / ((a > EPSF) ? a : 1.0f);
    float invc = 1.0f / ((c > EPSF) ? c : 1.0f);
    float ee2 = a + c - 2.0f*b;
    float invee2 = 1.0f / ((ee2 > EPSF) ? ee2 : 1.0f);
    float bma = b - a;
    float detp = detok ? det : -BIGF;
    float dz10 = e1z - e0z;
    // 2D projected determinant — exact-match path (no FMA contraction)
    float det2 = __fsub_rn(__fmul_rn(e0x, e1y), __fmul_rn(e1x, e0y));
    float ok2 = (fabsf(det2) > EPSF) ? 1.0f : 0.0f;
    float det2s = (fabsf(det2) > EPSF) ? det2 : 1.0f;

    float4* r = &g_face4[f * REC];
    r[0] = make_float4(-v0z, -v0z, e0z, e0z);
    r[1] = make_float4(e1z, e1z, a, a);
    r[2] = make_float4(-b, dz10, c, c);
    r[3] = make_float4(inva, inva, invc, invc);
    r[4] = make_float4(-invdet, -invdet, ee2, ee2);
    r[5] = make_float4(invee2, invee2, dz10, dz10);
    r[6] = make_float4(detp, detp, v0z, bma);
    r[7] = make_float4(v0x, v0y, e0x, e0y);
    r[8] = make_float4(e1x, e1y, det2s, ok2);
}

// ---------------- K3: phi grid (dominant kernel) ----------------
// 16 contiguous z per thread as 8 packed pairs (incremental wz chain),
// per-face parity via exact threshold count, uN/vN/dterm linearized in wz.
// grid: NSLICE*8 = 296 CTAs of 256 (= 2 CTAs/SM, one wave).
__global__ __launch_bounds__(256, 2) void k_phi(int F) {
    const int FS = (F + NSLICE - 1) / NSLICE;
    int s = blockIdx.x >> 3;
    int t = ((blockIdx.x & 7) << 8) | threadIdx.x;  // [0, 2048)
    int xy = t & 1023;
    int x  = t & 31;
    int y  = (t >> 5) & 31;
    int zhalf = t >> 10;                            // 0 or 1
    int zlo = zhalf << 4;                           // 0 or 16

    const float step = 2.0f / 31.0f;
    float px = grid_coord(x);
    float py = grid_coord(y);
    ull pz0pair = pack2(grid_coord(zlo), grid_coord(zlo + 1));
    ull step2x2;
    {
        float s2 = step + step;   // exact (x2)
        step2x2 = pack2(s2, s2);
    }

    ull acc2[8];
    #pragma unroll
    for (int j = 0; j < 8; j++) acc2[j] = pack2(BIGF, BIGF);
    unsigned par = 0;

    __shared__ float4 sf4[FCHUNK * REC];

    int fbeg = s * FS;
    int fend = min(F, fbeg + FS);
    for (int f0 = fbeg; f0 < fend; f0 += FCHUNK) {
        int nf = min(FCHUNK, fend - f0);
        __syncthreads();
        for (int i = threadIdx.x; i < nf * REC; i += 256)
            sf4[i] = g_face4[f0 * REC + i];
        __syncthreads();

        for (int j = 0; j < nf; j++) {
            const float4* r = &sf4[j * REC];
            float4 q0 = r[0], q1 = r[1], q2 = r[2], q3 = r[3], q4 = r[4];
            float4 q5 = r[5], q6 = r[6], q7 = r[7], q8 = r[8];

            float v0x = q7.x, v0y = q7.y, e0x = q7.z, e0y = q7.w;
            float e1x = q8.x, e1y = q8.y, det2s = q8.z, ok2 = q8.w;
            float v0z = q6.z, bma = q6.w, detp = q6.x;
            float e0z = q0.z, e1z = q1.x;
            float nb = q2.x, a = q1.z, c = q2.z;

            float wx = __fsub_rn(px, v0x);
            float wy = __fsub_rn(py, v0y);

            // --- ray cast: bit-matched to reference (IEEE div, no contraction) ---
            float nu = __fsub_rn(__fmul_rn(wx, e1y), __fmul_rn(wy, e1x));
            float nv = __fsub_rn(__fmul_rn(e0x, wy), __fmul_rn(e0y, wx));
            float u2 = __fdiv_rn(nu, det2s);
            float v2 = __fdiv_rn(nv, det2s);
            bool in2d = (u2 >= 0.0f) && (v2 >= 0.0f)
                     && (__fadd_rn(u2, v2) <= 1.0f) && (ok2 > 0.5f);
            float zint = __fadd_rn(__fadd_rn(v0z, __fmul_rn(u2, e0z)),
                                   __fmul_rn(v2, e1z));

            // --- exact hit-count threshold: thr = #{k in [0,32): pz[k] < zint} ---
            if (in2d) {
                int thr = __float2int_rd(fmaf(zint, 15.5f, 15.5f));
                thr = min(max(thr, 0), 32);
                while (thr < 32 && grid_coord(thr) < zint) thr++;
                while (thr > 0 && !(grid_coord(thr - 1) < zint)) thr--;
                int cnt = min(max(thr - zlo, 0), 16);
                par ^= (1u << cnt) - 1u;
            }

            // --- distance bases + linear coefficients (rounding-tolerant) ---
            float s0  = wx*e0x + wy*e0y;
            float s1  = wx*e1x + wy*e1y;
            float fxy = wx*wx + wy*wy;
            float dot2b = s1 - s0 - bma;
            float uN0 = c*s0 + nb*s1;
            float uNz = c*e0z + nb*e1z;
            float vN0 = a*s1 + nb*s0;
            float vNz = a*e1z + nb*e0z;
            float dt0 = detp - uN0 - vN0;
            float dtz = -(uNz + vNz);

            ull s02    = pack2(s0, s0);
            ull s12    = pack2(s1, s1);
            ull fxy2   = pack2(fxy, fxy);
            ull dot2b2 = pack2(dot2b, dot2b);
            ull uN02   = pack2(uN0, uN0);
            ull uNz2   = pack2(uNz, uNz);
            ull vN02   = pack2(vN0, vN0);
            ull vNz2   = pack2(vNz, vNz);
            ull dt02   = pack2(dt0, dt0);
            ull dtz2   = pack2(dtz, dtz);

            ull nv0z2 = pack2(q0.x, q0.y);
            ull e0z2  = pack2(q0.z, q0.w);
            ull e1z2  = pack2(q1.x, q1.y);
            ull a2    = pack2(q1.z, q1.w);
            ull c2    = pack2(q2.z, q2.w);
            ull inva2 = pack2(q3.x, q3.y);
            ull invc2 = pack2(q3.z, q3.w);
            ull nivd2 = pack2(q4.x, q4.y);
            ull ee22  = pack2(q4.z, q4.w);
            ull ivee2 = pack2(q5.x, q5.y);
            ull dz102 = pack2(q5.z, q5.w);

            ull wz2 = add2(pz0pair, nv0z2);
            #pragma unroll
            for (int jp = 0; jp < 8; jp++) {
                ull de02 = fma2(wz2, e0z2, s02);
                ull de12 = fma2(wz2, e1z2, s12);
                ull ff2  = fma2(wz2, wz2, fxy2);
                ull uN2  = fma2(wz2, uNz2, uN02);
                ull vN2  = fma2(wz2, vNz2, vN02);
                ull dterm = fma2(wz2, dtz2, dt02);
                // mask: == 0 iff inside triangle (det ok folded); < 0 otherwise
                ull mask = min2(min2(uN2, vN2), min2(dterm, ZERO2));
                ull ps2 = fma2(vN2, de12, mul2(uN2, de02));
                ull plane2 = fma2(nivd2, ps2, ff2);
                ull plane_m = fma2(mask, NEGBIG2, plane2);    // +huge outside
                ull m2de0 = mul2(de02, MTWO2);
                ull t02 = min2(max2(mul2(de02, inva2), ZERO2), ONE2);
                ull d02 = fma2(t02, fma2(t02, a2, m2de0), ff2);
                ull m2de1 = mul2(de12, MTWO2);
                ull t12 = min2(max2(mul2(de12, invc2), ZERO2), ONE2);
                ull d12 = fma2(t12, fma2(t12, c2, m2de1), ff2);
                ull dot22 = fma2(wz2, dz102, dot2b2);
                ull w1sq2 = add2(add2(ff2, a2), m2de0);
                ull t22 = min2(max2(mul2(dot22, ivee2), ZERO2), ONE2);
                ull d222 = fma2(t22, fma2(t22, ee22, mul2(dot22, MTWO2)), w1sq2);
                ull ed2 = min2(min2(d02, d12), d222);
                acc2[jp] = min2(acc2[jp], min2(ed2, plane_m));
                wz2 = add2(wz2, step2x2);
            }
        }
    }

    // store: 16 z values + parity word
    #pragma unroll
    for (int jp = 0; jp < 8; jp++) {
        float dlo, dhi;
        unpack2(dlo, dhi, acc2[jp]);
        dlo = fmaxf(dlo, 0.0f);    // clamp commutes with min: hoisted here
        dhi = fmaxf(dhi, 0.0f);
        int zA = zlo + 2*jp;
        g_d2[s * NPTS + (zA    ) * 1024 + xy] = dlo;
        g_d2[s * NPTS + (zA + 1) * 1024 + xy] = dhi;
    }
    g_par[s * (2 * NXY) + zhalf * NXY + xy] = par;
}

// ---------------- K4: combine slices -> phi (4 threads / point) ----------
__global__ void k_combine() {
    int gid = blockIdx.x * 256 + threadIdx.x;
    int n = gid >> 2;
    int lane = gid & 3;
    int z = n >> 10;
    int xy = n & 1023;
    int zhalf = z >> 4;
    int bit = z & 15;

    float d2 = BIGF;
    unsigned pp = 0;
    for (int s = lane; s < NSLICE; s += 4) {
        d2 = fminf(d2, g_d2[s * NPTS + n]);
        pp ^= g_par[s * (2 * NXY) + zhalf * NXY + xy];
    }
    #pragma unroll
    for (int o = 1; o < 4; o <<= 1) {
        d2 = fminf(d2, __shfl_xor_sync(0xFFFFFFFFu, d2, o));
        pp ^= __shfl_xor_sync(0xFFFFFFFFu, pp, o);
    }
    if (lane == 0)
        g_phi[n] = __fsqrt_rn(d2) * (((pp >> bit) & 1u) ? 1.0f : 0.0f);
}

// ---------------- K5: trilinear sample -> partial sums (32 CTAs x 128) -------
__global__ void k_lossp(const float* __restrict__ ov, int no) {
    __shared__ float wsum[4];
    int t = threadIdx.x;
    float cx = g_params[0], cy = g_params[1], cz = g_params[2];
    float sc = g_params[3];
    float acc = 0.0f;
    for (int i = blockIdx.x * 128 + t; i < no; i += 32 * 128) {
        float qx = __fdiv_rn(__fsub_rn(ov[i*3+0], cx), sc);
        float qy = __fdiv_rn(__fsub_rn(ov[i*3+1], cy), sc);
        float qz = __fdiv_rn(__fsub_rn(ov[i*3+2], cz), sc);
        float fx = __fmul_rn(__fmul_rn(__fadd_rn(qx, 1.0f), 0.5f), (float)(G - 1));
        float fy = __fmul_rn(__fmul_rn(__fadd_rn(qy, 1.0f), 0.5f), (float)(G - 1));
        float fz = __fmul_rn(__fmul_rn(__fadd_rn(qz, 1.0f), 0.5f), (float)(G - 1));
        float flx = floorf(fx), fly = floorf(fy), flz = floorf(fz);
        int ix0 = (int)flx, iy0 = (int)fly, iz0 = (int)flz;
        float wx1 = __fsub_rn(fx, flx), wy1 = __fsub_rn(fy, fly), wz1 = __fsub_rn(fz, flz);
        float wx0 = __fsub_rn(1.0f, wx1), wy0 = __fsub_rn(1.0f, wy1), wz0 = __fsub_rn(1.0f, wz1);
        float val = 0.0f;
        #pragma unroll
        for (int dz = 0; dz < 2; dz++) {
            #pragma unroll
            for (int dy = 0; dy < 2; dy++) {
                #pragma unroll
                for (int dx = 0; dx < 2; dx++) {
                    int ix = ix0 + dx, iy = iy0 + dy, iz = iz0 + dz;
                    bool valid = (ix >= 0) && (ix < G) && (iy >= 0) && (iy < G)
                              && (iz >= 0) && (iz < G);
                    int cix = min(max(ix, 0), G-1);
                    int ciy = min(max(iy, 0), G-1);
                    int ciz = min(max(iz, 0), G-1);
                    float pv = g_phi[(ciz * G + ciy) * G + cix];
                    float w = __fmul_rn(__fmul_rn(dx ? wx1 : wx0, dy ? wy1 : wy0),
                                        dz ? wz1 : wz0);
                    val = __fadd_rn(val, valid ? __fmul_rn(pv, w) : 0.0f);
                }
            }
        }
        acc += val;
    }
    // warp reduce (fixed order)
    #pragma unroll
    for (int o = 16; o > 0; o >>= 1)
        acc += __shfl_down_sync(0xFFFFFFFFu, acc, o);
    if ((t & 31) == 0) wsum[t >> 5] = acc;
    __syncthreads();
    if (t == 0)
        g_lpart[blockIdx.x] = ((wsum[0] + wsum[1]) + wsum[2]) + wsum[3];
}

// ---------------- K6: final ----------------
__global__ void k_final(float* __restrict__ out) {
    if (threadIdx.x == 0) {
        float sum = 0.0f;
        #pragma unroll
        for (int i = 0; i < 32; i++) sum += g_lpart[i];
        float loss = __fmul_rn(sum, sum);
        out[0] = (g_params[4] > 0.5f) ? loss : 0.0f;
    }
}

// ---------------- launch ----------------
extern "C" void kernel_launch(void* const* d_in, const int* in_sizes, int n_in,
                              void* d_out, int out_size) {
    const float* hv    = (const float*)d_in[0];
    const float* ov    = (const float*)d_in[1];
    const int*   faces = (const int*)d_in[2];
    int nh = in_sizes[0] / 3;
    int no = in_sizes[1] / 3;
    int F  = in_sizes[2] / 3;
    if (F > MAXF) F = MAXF;

    k_bbox<<<1, 256>>>(hv, nh, ov, no);
    k_faces<<<(F + 127) / 128, 128>>>(hv, faces, F);
    k_phi<<<NSLICE * 8, 256>>>(F);
    k_combine<<<(NPTS * 4) / 256, 256>>>();
    k_lossp<<<32, 128>>>(ov, no);
    k_final<<<1, 32>>>((float*)d_out);
}